// round 1
// baseline (speedup 1.0000x reference)
#include <cuda_runtime.h>

// ---------------- scratch (no allocations allowed) ----------------
#define NTOK (2*4096)              // 8192 tokens
__device__ float g_xt[NTOK*64];    // x in NHWC
__device__ float g_b1[NTOK*64];    // conv1 output (relu), NHWC
__device__ float g_t [NTOK*64];    // conv2 output (= h = t), NHWC
__device__ float g_wt1[64*9*64];   // conv1 weights [ci][k][co]
__device__ float g_wt2[64*9*64];   // conv2 weights [ci][k][co]

__device__ __forceinline__ float ex2f(float x) {
    float y; asm("ex2.approx.f32 %0, %1;" : "=f"(y) : "f"(x)); return y;
}

// ---------------- prep: NCHW -> NHWC transpose of x ----------------
__global__ void k_transpose_x(const float* __restrict__ x) {
    __shared__ float tile[32][33];
    int b  = blockIdx.z;
    int c0 = blockIdx.y * 32;
    int s0 = blockIdx.x * 32;
    int tx = threadIdx.x, ty = threadIdx.y;
#pragma unroll
    for (int i = 0; i < 32; i += 8)
        tile[ty + i][tx] = x[(b*64 + c0 + ty + i) * 4096 + s0 + tx];
    __syncthreads();
#pragma unroll
    for (int i = 0; i < 32; i += 8)
        g_xt[(b*4096 + s0 + ty + i) * 64 + c0 + tx] = tile[tx][ty + i];
}

// ---------------- prep: conv weights [co][ci][3][3] -> [ci][k][co] ----------------
__global__ void k_transpose_w(const float* __restrict__ w1, const float* __restrict__ w2) {
    int i = blockIdx.x * blockDim.x + threadIdx.x;
    if (i >= 2 * 36864) return;
    const float* w = (i < 36864) ? w1 : w2;
    float* dst     = (i < 36864) ? g_wt1 : g_wt2;
    int o  = (i < 36864) ? i : (i - 36864);
    int ci = o / 576;
    int k  = (o % 576) / 64;
    int co = o & 63;
    dst[o] = w[co * 576 + ci * 9 + k];
}

// ---------------- conv3x3 (NHWC in/out), 64->64 channels ----------------
// block: (64 co, 2 rows); tile: 8 px in x, 2 rows, all 64 co. grid (8,32,2) = 512 blocks.
template<bool RELU, int SRC>
__global__ void __launch_bounds__(128) k_conv(const float* __restrict__ bias) {
    const float* __restrict__ in  = (SRC == 0) ? g_xt  : g_b1;
    const float* __restrict__ wt  = (SRC == 0) ? g_wt1 : g_wt2;
    float* __restrict__       out = (SRC == 0) ? g_b1  : g_t;

    __shared__ float w_s[4608];        // 8 ci x 9 k x 64 co
    __shared__ float in_s[8][4][10];   // [ci'][row y0-1..y0+2][x0-1..x0+8]

    int tx = threadIdx.x, ty = threadIdx.y;
    int tid = ty * 64 + tx;
    int x0 = blockIdx.x * 8, y0 = blockIdx.y * 2, b = blockIdx.z;

    float acc[8];
#pragma unroll
    for (int p = 0; p < 8; p++) acc[p] = 0.f;

    for (int ci0 = 0; ci0 < 64; ci0 += 8) {
        __syncthreads();
        // weights: 4608 = 36 * 128, fully coalesced
#pragma unroll 4
        for (int i = 0; i < 36; i++)
            w_s[tid + i * 128] = wt[ci0 * 576 + tid + i * 128];
        // input tile: 8*4*10 = 320 elems, zero-padded at borders
        for (int e = tid; e < 320; e += 128) {
            int ci = e & 7, xx = (e >> 3) % 10, r = e / 80;
            int y = y0 - 1 + r, xg = x0 - 1 + xx;
            float v = 0.f;
            if ((unsigned)y < 64u && (unsigned)xg < 64u)
                v = in[((b * 64 + y) * 64 + xg) * 64 + ci0 + ci];
            in_s[ci][r][xx] = v;
        }
        __syncthreads();

#pragma unroll
        for (int ci = 0; ci < 8; ci++) {
            float w0 = w_s[(ci*9+0)*64+tx], w1 = w_s[(ci*9+1)*64+tx], w2 = w_s[(ci*9+2)*64+tx];
            float w3 = w_s[(ci*9+3)*64+tx], w4 = w_s[(ci*9+4)*64+tx], w5 = w_s[(ci*9+5)*64+tx];
            float w6 = w_s[(ci*9+6)*64+tx], w7 = w_s[(ci*9+7)*64+tx], w8 = w_s[(ci*9+8)*64+tx];
            float a0[10], a1[10], a2[10];
#pragma unroll
            for (int xx = 0; xx < 10; xx++) {
                a0[xx] = in_s[ci][ty + 0][xx];
                a1[xx] = in_s[ci][ty + 1][xx];
                a2[xx] = in_s[ci][ty + 2][xx];
            }
#pragma unroll
            for (int p = 0; p < 8; p++) {
                float s = acc[p];
                s = fmaf(w0, a0[p], s); s = fmaf(w1, a0[p+1], s); s = fmaf(w2, a0[p+2], s);
                s = fmaf(w3, a1[p], s); s = fmaf(w4, a1[p+1], s); s = fmaf(w5, a1[p+2], s);
                s = fmaf(w6, a2[p], s); s = fmaf(w7, a2[p+1], s); s = fmaf(w8, a2[p+2], s);
                acc[p] = s;
            }
        }
    }

    float bv = bias[tx];
    int y = y0 + ty;
#pragma unroll
    for (int p = 0; p < 8; p++) {
        float o = acc[p] + bv;
        if (RELU) o = fmaxf(o, 0.f);
        out[((b * 64 + y) * 64 + x0 + p) * 64 + tx] = o;   // coalesced: lanes = co
    }
}

// ---------------- attention: 32 tokens per block, 256 threads ----------------
// out_c = sum_d exp(q_c k_d) v_d / sum_d exp(q_c k_d);  final = Wo out + bo + t
#define SMEM_FLOATS (4*4160 + 4*2080)   // 24960 floats = 99840 bytes
__global__ void __launch_bounds__(256) k_attn(
    const float* __restrict__ wq, const float* __restrict__ wk,
    const float* __restrict__ wv, const float* __restrict__ wo,
    const float* __restrict__ bo, float* __restrict__ out)
{
    extern __shared__ float sm[];
    float* wq_s = sm;                  // [l][c], row pad 65
    float* wk_s = sm + 4160;
    float* wv_s = sm + 8320;
    float* wo_s = sm + 12480;          // [c][c'], row pad 65
    float* t_s  = sm + 16640;          // [32][65]
    float* k_s  = t_s + 2080;
    float* v_s  = k_s + 2080;
    float* o_s  = v_s + 2080;

    int tid = threadIdx.x;
    int n0  = blockIdx.x * 32;

    // weights: read coalesced [c][l], write transposed (pad-65 kills bank conflicts)
#pragma unroll 4
    for (int i = 0; i < 16; i++) {
        int g = tid + i * 256;
        int c = g >> 6, l = g & 63;
        wq_s[l * 65 + c] = wq[g];
        wk_s[l * 65 + c] = wk[g];
        wv_s[l * 65 + c] = wv[g];
        wo_s[l * 65 + c] = wo[g];
    }
#pragma unroll
    for (int i = 0; i < 8; i++) {
        int g = tid + i * 256;
        t_s[(g >> 6) * 65 + (g & 63)] = g_t[n0 * 64 + g];
    }
    __syncthreads();

    // phase 1: q/k/v matvecs. thread = (token tt, 8-channel group c0)
    int tt = tid >> 3, cg = tid & 7, c0 = cg * 8;
    float q[8], kk[8], vv[8];
#pragma unroll
    for (int j = 0; j < 8; j++) { q[j] = 0.f; kk[j] = 0.f; vv[j] = 0.f; }
    const float* trow = t_s + tt * 65;
#pragma unroll 4
    for (int l = 0; l < 64; l++) {
        float tl = trow[l];
        const float* wql = wq_s + l * 65 + c0;
        const float* wkl = wk_s + l * 65 + c0;
        const float* wvl = wv_s + l * 65 + c0;
#pragma unroll
        for (int j = 0; j < 8; j++) {
            q[j]  = fmaf(tl, wql[j], q[j]);
            kk[j] = fmaf(tl, wkl[j], kk[j]);
            vv[j] = fmaf(tl, wvl[j], vv[j]);
        }
    }
    // L2 norms over the 8-lane token group
    float sq = 0.f, sk = 0.f;
#pragma unroll
    for (int j = 0; j < 8; j++) { sq = fmaf(q[j], q[j], sq); sk = fmaf(kk[j], kk[j], sk); }
#pragma unroll
    for (int off = 1; off < 8; off <<= 1) {
        sq += __shfl_xor_sync(0xffffffffu, sq, off);
        sk += __shfl_xor_sync(0xffffffffu, sk, off);
    }
    const float LOG2E = 1.4426950408889634f;
    float invq = LOG2E / fmaxf(sqrtf(sq), 1e-12f);   // fold log2(e) into q
    float invk = 1.0f  / fmaxf(sqrtf(sk), 1e-12f);
#pragma unroll
    for (int j = 0; j < 8; j++) {
        q[j] *= invq;
        k_s[tt * 65 + c0 + j] = kk[j] * invk;
        v_s[tt * 65 + c0 + j] = vv[j];
    }
    __syncthreads();

    // phase 2: rank-1 softmax-attention, 2^(qs_c * k_d)
    float num[8], den[8];
#pragma unroll
    for (int j = 0; j < 8; j++) { num[j] = 0.f; den[j] = 0.f; }
    const float* krow = k_s + tt * 65;
    const float* vrow = v_s + tt * 65;
#pragma unroll 2
    for (int d = 0; d < 64; d++) {
        float kd = krow[d];
        float vd = vrow[d];
#pragma unroll
        for (int j = 0; j < 8; j++) {
            float e = ex2f(q[j] * kd);
            num[j] = fmaf(e, vd, num[j]);
            den[j] += e;
        }
    }
#pragma unroll
    for (int j = 0; j < 8; j++)
        o_s[tt * 65 + c0 + j] = __fdividef(num[j], den[j]);
    __syncthreads();

    // phase 3: out-projection + bias + residual; remap for coalesced NCHW stores
    int tok2 = tid & 31, cg2 = tid >> 5, cp = cg2 * 8;
    float fin[8];
#pragma unroll
    for (int j = 0; j < 8; j++) fin[j] = 0.f;
    const float* orow = o_s + tok2 * 65;
#pragma unroll 4
    for (int c = 0; c < 64; c++) {
        float oc = orow[c];
        const float* wol = wo_s + c * 65 + cp;
#pragma unroll
        for (int j = 0; j < 8; j++) fin[j] = fmaf(oc, wol[j], fin[j]);
    }
    int b = n0 >> 12;
    int s = (n0 & 4095) + tok2;
#pragma unroll
    for (int j = 0; j < 8; j++) {
        float r = fin[j] + bo[cp + j] + t_s[tok2 * 65 + cp + j];
        out[(b * 64 + cp + j) * 4096 + s] = r;   // lanes = consecutive tokens -> 128B stores
    }
}

// ---------------- launch ----------------
extern "C" void kernel_launch(void* const* d_in, const int* in_sizes, int n_in,
                              void* d_out, int out_size) {
    const float* x  = (const float*)d_in[0];
    const float* w1 = (const float*)d_in[1];
    const float* b1 = (const float*)d_in[2];
    const float* w2 = (const float*)d_in[3];
    const float* b2 = (const float*)d_in[4];
    const float* wq = (const float*)d_in[5];
    const float* wk = (const float*)d_in[6];
    const float* wv = (const float*)d_in[7];
    const float* wo = (const float*)d_in[8];
    const float* bo = (const float*)d_in[9];
    float* out = (float*)d_out;

    cudaFuncSetAttribute(k_attn, cudaFuncAttributeMaxDynamicSharedMemorySize,
                         SMEM_FLOATS * (int)sizeof(float));

    k_transpose_x<<<dim3(128, 2, 2), dim3(32, 8)>>>(x);
    k_transpose_w<<<(2 * 36864 + 255) / 256, 256>>>(w1, w2);
    k_conv<true,  0><<<dim3(8, 32, 2), dim3(64, 2)>>>(b1);
    k_conv<false, 1><<<dim3(8, 32, 2), dim3(64, 2)>>>(b2);
    k_attn<<<256, 256, SMEM_FLOATS * (int)sizeof(float)>>>(wq, wk, wv, wo, bo, out);
}

// round 2
// speedup vs baseline: 1.3575x; 1.3575x over previous
#include <cuda_runtime.h>

// ---------------- scratch (no allocations allowed) ----------------
#define NTOK (2*4096)              // 8192 tokens
__device__ float g_xt[NTOK*64];    // x in NHWC
__device__ float g_b1[NTOK*64];    // conv1 output (relu), NHWC
__device__ float g_t [NTOK*64];    // conv2 output (= h = t), NHWC
__device__ float g_wt1[64*9*64];   // conv1 weights [ci][k][co]
__device__ float g_wt2[64*9*64];   // conv2 weights [ci][k][co]

__device__ __forceinline__ float ex2f(float x) {
    float y; asm("ex2.approx.f32 %0, %1;" : "=f"(y) : "f"(x)); return y;
}

// ---------------- prep: NCHW -> NHWC transpose of x ----------------
__global__ void k_transpose_x(const float* __restrict__ x) {
    __shared__ float tile[32][33];
    int b  = blockIdx.z;
    int c0 = blockIdx.y * 32;
    int s0 = blockIdx.x * 32;
    int tx = threadIdx.x, ty = threadIdx.y;
#pragma unroll
    for (int i = 0; i < 32; i += 8)
        tile[ty + i][tx] = x[(b*64 + c0 + ty + i) * 4096 + s0 + tx];
    __syncthreads();
#pragma unroll
    for (int i = 0; i < 32; i += 8)
        g_xt[(b*4096 + s0 + ty + i) * 64 + c0 + tx] = tile[tx][ty + i];
}

// ---------------- prep: conv weights [co][ci][3][3] -> [ci][k][co] ----------------
__global__ void k_transpose_w(const float* __restrict__ w1, const float* __restrict__ w2) {
    int i = blockIdx.x * blockDim.x + threadIdx.x;
    if (i >= 2 * 36864) return;
    const float* w = (i < 36864) ? w1 : w2;
    float* dst     = (i < 36864) ? g_wt1 : g_wt2;
    int o  = (i < 36864) ? i : (i - 36864);
    int ci = o / 576;
    int k  = (o % 576) / 64;
    int co = o & 63;
    dst[o] = w[co * 576 + ci * 9 + k];
}

// ---------------- conv3x3 (NHWC in/out), 64->64 channels ----------------
// block: 256 threads = 64 co x 4 groups (row r in 0..1, half h in 0..1).
// tile: 2 rows x 16 px, all 64 co. grid (4,32,2) = 256 blocks.
// double-buffered ci chunks of 8; weights via float2, inputs via float4 LDS.
template<bool RELU, int SRC>
__global__ void __launch_bounds__(256) k_conv(const float* __restrict__ bias) {
    const float* __restrict__ in  = (SRC == 0) ? g_xt  : g_b1;
    const float* __restrict__ wt  = (SRC == 0) ? g_wt1 : g_wt2;
    float* __restrict__       out = (SRC == 0) ? g_b1  : g_t;

    __shared__ float w_s[2][4608];       // 8 ci x 9 k x 64 co
    __shared__ float in_s[2][8][88];     // [ci][r*20 + xx], r<4, xx<18 (pad for banks/align)

    const int tid = threadIdx.x;
    const int co  = tid & 63;
    const int g   = tid >> 6;            // 0..3
    const int r_o = g >> 1;              // output row within tile (0..1)
    const int h   = g & 1;               // px half (0..1)
    const int x0 = blockIdx.x * 16, y0 = blockIdx.y * 2, b = blockIdx.z;

    // staging thread mapping (inputs): 144 active threads
    const int s_ci = tid & 7;
    const int s_xx = tid >> 3;           // 0..31, active when <18
    const int s_xg = x0 - 1 + s_xx;
    const bool s_act = (s_xx < 18);

    float acc[8];
#pragma unroll
    for (int p = 0; p < 8; p++) acc[p] = 0.f;

    // stage chunk c (ci0 = 8c) into buffer bufi
    auto stage = [&](int c, int bufi) {
        const float2* wsrc = (const float2*)(wt + c * 4608);
        float2* wdst = (float2*)w_s[bufi];
#pragma unroll
        for (int i = 0; i < 9; i++)
            wdst[tid + i * 256] = wsrc[tid + i * 256];
        if (s_act) {
#pragma unroll
            for (int r = 0; r < 4; r++) {
                int y = y0 - 1 + r;
                float v = 0.f;
                if ((unsigned)y < 64u && (unsigned)s_xg < 64u)
                    v = in[((b * 64 + y) * 64 + s_xg) * 64 + c * 8 + s_ci];
                in_s[bufi][s_ci][r * 20 + s_xx] = v;
            }
        }
    };

    stage(0, 0);
    __syncthreads();

#pragma unroll
    for (int c = 0; c < 8; c++) {
        const int bufi = c & 1;
        if (c < 7) stage(c + 1, bufi ^ 1);

        const float* wb = w_s[bufi];
        const float* ib = &in_s[bufi][0][0];
#pragma unroll
        for (int ci = 0; ci < 8; ci++) {
            const float* wrow = wb + ci * 576 + co;
            const float* irow = ib + ci * 88 + r_o * 20 + h * 8;
#pragma unroll
            for (int dy = 0; dy < 3; dy++) {
                float w0 = wrow[(dy * 3 + 0) * 64];
                float w1 = wrow[(dy * 3 + 1) * 64];
                float w2 = wrow[(dy * 3 + 2) * 64];
                const float4* ip = (const float4*)(irow + dy * 20);
                float4 v0 = ip[0], v1 = ip[1], v2 = ip[2];
                float a[12] = {v0.x, v0.y, v0.z, v0.w,
                               v1.x, v1.y, v1.z, v1.w,
                               v2.x, v2.y, v2.z, v2.w};
#pragma unroll
                for (int p = 0; p < 8; p++)
                    acc[p] = fmaf(w0, a[p],
                             fmaf(w1, a[p + 1],
                             fmaf(w2, a[p + 2], acc[p])));
            }
        }
        __syncthreads();
    }

    float bv = bias[co];
    int y = y0 + r_o;
    int base = ((b * 64 + y) * 64 + x0 + h * 8) * 64 + co;
#pragma unroll
    for (int p = 0; p < 8; p++) {
        float o = acc[p] + bv;
        if (RELU) o = fmaxf(o, 0.f);
        out[base + p * 64] = o;          // lanes = co -> coalesced
    }
}

// ---------------- attention: 32 tokens per block, 256 threads ----------------
// out_c = sum_d exp(q_c k_d) v_d / sum_d exp(q_c k_d);  final = Wo out + bo + t
#define SMEM_FLOATS (4*4160 + 4*2080)   // 24960 floats = 99840 bytes
__global__ void __launch_bounds__(256) k_attn(
    const float* __restrict__ wq, const float* __restrict__ wk,
    const float* __restrict__ wv, const float* __restrict__ wo,
    const float* __restrict__ bo, float* __restrict__ out)
{
    extern __shared__ float sm[];
    float* wq_s = sm;                  // [l][c], row pad 65
    float* wk_s = sm + 4160;
    float* wv_s = sm + 8320;
    float* wo_s = sm + 12480;          // [c][c'], row pad 65
    float* t_s  = sm + 16640;          // [32][65]
    float* k_s  = t_s + 2080;
    float* v_s  = k_s + 2080;
    float* o_s  = v_s + 2080;

    int tid = threadIdx.x;
    int n0  = blockIdx.x * 32;

    // weights: read coalesced [c][l], write transposed (pad-65 kills bank conflicts)
#pragma unroll 4
    for (int i = 0; i < 16; i++) {
        int g = tid + i * 256;
        int c = g >> 6, l = g & 63;
        wq_s[l * 65 + c] = wq[g];
        wk_s[l * 65 + c] = wk[g];
        wv_s[l * 65 + c] = wv[g];
        wo_s[l * 65 + c] = wo[g];
    }
#pragma unroll
    for (int i = 0; i < 8; i++) {
        int g = tid + i * 256;
        t_s[(g >> 6) * 65 + (g & 63)] = g_t[n0 * 64 + g];
    }
    __syncthreads();

    // phase 1: q/k/v matvecs. thread = (token tt, 8-channel group c0)
    int tt = tid >> 3, cg = tid & 7, c0 = cg * 8;
    float q[8], kk[8], vv[8];
#pragma unroll
    for (int j = 0; j < 8; j++) { q[j] = 0.f; kk[j] = 0.f; vv[j] = 0.f; }
    const float* trow = t_s + tt * 65;
#pragma unroll 4
    for (int l = 0; l < 64; l++) {
        float tl = trow[l];
        const float* wql = wq_s + l * 65 + c0;
        const float* wkl = wk_s + l * 65 + c0;
        const float* wvl = wv_s + l * 65 + c0;
#pragma unroll
        for (int j = 0; j < 8; j++) {
            q[j]  = fmaf(tl, wql[j], q[j]);
            kk[j] = fmaf(tl, wkl[j], kk[j]);
            vv[j] = fmaf(tl, wvl[j], vv[j]);
        }
    }
    // L2 norms over the 8-lane token group
    float sq = 0.f, sk = 0.f;
#pragma unroll
    for (int j = 0; j < 8; j++) { sq = fmaf(q[j], q[j], sq); sk = fmaf(kk[j], kk[j], sk); }
#pragma unroll
    for (int off = 1; off < 8; off <<= 1) {
        sq += __shfl_xor_sync(0xffffffffu, sq, off);
        sk += __shfl_xor_sync(0xffffffffu, sk, off);
    }
    const float LOG2E = 1.4426950408889634f;
    float invq = LOG2E / fmaxf(sqrtf(sq), 1e-12f);   // fold log2(e) into q
    float invk = 1.0f  / fmaxf(sqrtf(sk), 1e-12f);
#pragma unroll
    for (int j = 0; j < 8; j++) {
        q[j] *= invq;
        k_s[tt * 65 + c0 + j] = kk[j] * invk;
        v_s[tt * 65 + c0 + j] = vv[j];
    }
    __syncthreads();

    // phase 2: rank-1 softmax-attention, 2^(qs_c * k_d)
    float num[8], den[8];
#pragma unroll
    for (int j = 0; j < 8; j++) { num[j] = 0.f; den[j] = 0.f; }
    const float* krow = k_s + tt * 65;
    const float* vrow = v_s + tt * 65;
#pragma unroll 2
    for (int d = 0; d < 64; d++) {
        float kd = krow[d];
        float vd = vrow[d];
#pragma unroll
        for (int j = 0; j < 8; j++) {
            float e = ex2f(q[j] * kd);
            num[j] = fmaf(e, vd, num[j]);
            den[j] += e;
        }
    }
#pragma unroll
    for (int j = 0; j < 8; j++)
        o_s[tt * 65 + c0 + j] = __fdividef(num[j], den[j]);
    __syncthreads();

    // phase 3: out-projection + bias + residual; remap for coalesced NCHW stores
    int tok2 = tid & 31, cg2 = tid >> 5, cp = cg2 * 8;
    float fin[8];
#pragma unroll
    for (int j = 0; j < 8; j++) fin[j] = 0.f;
    const float* orow = o_s + tok2 * 65;
#pragma unroll 4
    for (int c = 0; c < 64; c++) {
        float oc = orow[c];
        const float* wol = wo_s + c * 65 + cp;
#pragma unroll
        for (int j = 0; j < 8; j++) fin[j] = fmaf(oc, wol[j], fin[j]);
    }
    int b = n0 >> 12;
    int s = (n0 & 4095) + tok2;
#pragma unroll
    for (int j = 0; j < 8; j++) {
        float r = fin[j] + bo[cp + j] + t_s[tok2 * 65 + cp + j];
        out[(b * 64 + cp + j) * 4096 + s] = r;   // lanes = consecutive tokens -> 128B stores
    }
}

// ---------------- launch ----------------
extern "C" void kernel_launch(void* const* d_in, const int* in_sizes, int n_in,
                              void* d_out, int out_size) {
    const float* x  = (const float*)d_in[0];
    const float* w1 = (const float*)d_in[1];
    const float* b1 = (const float*)d_in[2];
    const float* w2 = (const float*)d_in[3];
    const float* b2 = (const float*)d_in[4];
    const float* wq = (const float*)d_in[5];
    const float* wk = (const float*)d_in[6];
    const float* wv = (const float*)d_in[7];
    const float* wo = (const float*)d_in[8];
    const float* bo = (const float*)d_in[9];
    float* out = (float*)d_out;

    cudaFuncSetAttribute(k_attn, cudaFuncAttributeMaxDynamicSharedMemorySize,
                         SMEM_FLOATS * (int)sizeof(float));

    k_transpose_x<<<dim3(128, 2, 2), dim3(32, 8)>>>(x);
    k_transpose_w<<<(2 * 36864 + 255) / 256, 256>>>(w1, w2);
    k_conv<true,  0><<<dim3(4, 32, 2), dim3(256)>>>(b1);
    k_conv<false, 1><<<dim3(4, 32, 2), dim3(256)>>>(b2);
    k_attn<<<256, 256, SMEM_FLOATS * (int)sizeof(float)>>>(wq, wk, wv, wo, bo, out);
}